// round 10
// baseline (speedup 1.0000x reference)
#include <cuda_runtime.h>
#include <cstdint>

// Problem constants: B=8, H=16, S=1024, D=64.
#define Bb 8
#define Hh 16
#define Ss 1024
#define Dd 64

struct K2 { uint32_t a, b; };

__host__ __device__ constexpr uint32_t rotl_c(uint32_t x, int r) {
    return (x << r) | (x >> (32 - r));
}

// constexpr threefry2x32 for compile-time folded key
constexpr K2 threefry_host(uint32_t k0, uint32_t k1, uint32_t c0, uint32_t c1) {
    uint32_t ks[3] = { k0, k1, 0x1BD11BDAu ^ k0 ^ k1 };
    uint32_t x0 = c0 + ks[0], x1 = c1 + ks[1];
    const int rot[8] = {13, 15, 26, 6, 17, 29, 16, 24};
    for (int g = 0; g < 5; ++g) {
        for (int i = 0; i < 4; ++i) {
            x0 += x1;
            x1 = rotl_c(x1, rot[(g & 1) * 4 + i]);
            x1 ^= x0;
        }
        x0 += ks[(g + 1) % 3];
        x1 += ks[(g + 2) % 3] + (uint32_t)(g + 1);
    }
    return { x0, x1 };
}

// JAX partitionable threefry: counter (0, idx), bits = x0 ^ x1
__device__ __forceinline__ uint32_t jax_bits(uint32_t idx, uint32_t k0, uint32_t k1) {
    const uint32_t ks2 = 0x1BD11BDAu ^ k0 ^ k1;
    uint32_t x0 = k0;
    uint32_t x1 = idx + k1;
#define TF_RND(r) { x0 += x1; x1 = __funnelshift_l(x1, x1, (r)); x1 ^= x0; }
    TF_RND(13) TF_RND(15) TF_RND(26) TF_RND(6)   x0 += k1;  x1 += ks2 + 1u;
    TF_RND(17) TF_RND(29) TF_RND(16) TF_RND(24)  x0 += ks2; x1 += k0 + 2u;
    TF_RND(13) TF_RND(15) TF_RND(26) TF_RND(6)   x0 += k0;  x1 += k1 + 3u;
    TF_RND(17) TF_RND(29) TF_RND(16) TF_RND(24)  x0 += k1;  x1 += ks2 + 4u;
    TF_RND(13) TF_RND(15) TF_RND(26) TF_RND(6)   x0 += ks2; x1 += k0 + 5u;
#undef TF_RND
    return x0 ^ x1;
}
// keep iff uniform(bits) < 0.9f  ⟺  bits < 0xE6666600  (exact integer form)
#define KEEP_THRESH 0xE6666600u

__device__ __forceinline__ uint32_t f2tf(float x) {
    uint32_t r;
    asm("cvt.rna.tf32.f32 %0, %1;" : "=r"(r) : "f"(x));
    return r;
}

#define MMA_TF32(d0,d1,d2,d3,a0,a1,a2,a3,b0,b1)                               \
    asm volatile("mma.sync.aligned.m16n8k8.row.col.f32.tf32.tf32.f32 "        \
                 "{%0,%1,%2,%3},{%4,%5,%6,%7},{%8,%9},{%0,%1,%2,%3};"         \
                 : "+f"(d0), "+f"(d1), "+f"(d2), "+f"(d3)                     \
                 : "r"(a0), "r"(a1), "r"(a2), "r"(a3), "r"(b0), "r"(b1))

// per-row exp-sum partials: [B*H*S rows][32 col-blocks of 32]
__device__ float g_rowsum[(size_t)Bb * Hh * Ss * 32];

// ============================================================================
// K_A: e = mask ? exp((Q K^T)/8) : 0  -> Attn buffer, + partial exp-sums.
// (proven R8 version, unchanged)
// ============================================================================
#define QKS 68
#define QK_SMEM_BYTES ((128 * QKS + 2 * 64 * QKS) * 4)

extern "C" __global__ void __launch_bounds__(256)
qk_kernel(const float* __restrict__ Q, const float* __restrict__ K,
          const int* __restrict__ M, float* __restrict__ Attn)
{
    extern __shared__ float sm[];
    float*    sQ  = sm;                                   // 128*68
    uint32_t* sKh = (uint32_t*)(sm + 128 * QKS);          // 64*68
    float*    sKl = (float*)(sKh + 64 * QKS);             // 64*68

    const int kt = blockIdx.x, qt = blockIdx.y, bh = blockIdx.z;
    const int b  = bh >> 4;
    const int tid = threadIdx.x;
    const int w = tid >> 5, lane = tid & 31, g = lane >> 2, tig = lane & 3;

    const float* Qg = Q + ((size_t)bh * Ss + qt * 128) * Dd;
    const float* Kg = K + ((size_t)bh * Ss + kt * 64) * Dd;

    for (int i = tid; i < 128 * 16; i += 256) {
        int row = i >> 4, c4 = (i & 15) * 4;
        float4 v = ((const float4*)Qg)[i];
        float* p = sQ + row * QKS + c4;
        p[0] = v.x * 0.125f; p[1] = v.y * 0.125f;
        p[2] = v.z * 0.125f; p[3] = v.w * 0.125f;
    }
    for (int i = tid; i < 64 * 16; i += 256) {
        int row = i >> 4, c4 = (i & 15) * 4;
        float4 v = ((const float4*)Kg)[i];
        uint32_t* ph = sKh + row * QKS + c4;
        float*    pl = sKl + row * QKS + c4;
        uint32_t h0 = f2tf(v.x), h1 = f2tf(v.y), h2 = f2tf(v.z), h3 = f2tf(v.w);
        ph[0] = h0; ph[1] = h1; ph[2] = h2; ph[3] = h3;
        pl[0] = v.x - __uint_as_float(h0); pl[1] = v.y - __uint_as_float(h1);
        pl[2] = v.z - __uint_as_float(h2); pl[3] = v.w - __uint_as_float(h3);
    }
    __syncthreads();

    const int mblk = (w & 3) * 32;
    const int nblk = (w >> 2) * 32;

    float acc[2][4][4];
    #pragma unroll
    for (int mt = 0; mt < 2; ++mt)
        #pragma unroll
        for (int nt = 0; nt < 4; ++nt)
            #pragma unroll
            for (int j = 0; j < 4; ++j) acc[mt][nt][j] = 0.f;

    #pragma unroll
    for (int ks = 0; ks < 8; ++ks) {
        uint32_t Ah[2][4], Al[2][4];
        #pragma unroll
        for (int mt = 0; mt < 2; ++mt) {
            const int r = mblk + mt * 16;
            const int c = ks * 8 + tig;
            float v0 = sQ[(r + g) * QKS + c];
            float v1 = sQ[(r + g + 8) * QKS + c];
            float v2 = sQ[(r + g) * QKS + c + 4];
            float v3 = sQ[(r + g + 8) * QKS + c + 4];
            Ah[mt][0] = f2tf(v0); Al[mt][0] = __float_as_uint(v0 - __uint_as_float(Ah[mt][0]));
            Ah[mt][1] = f2tf(v1); Al[mt][1] = __float_as_uint(v1 - __uint_as_float(Ah[mt][1]));
            Ah[mt][2] = f2tf(v2); Al[mt][2] = __float_as_uint(v2 - __uint_as_float(Ah[mt][2]));
            Ah[mt][3] = f2tf(v3); Al[mt][3] = __float_as_uint(v3 - __uint_as_float(Ah[mt][3]));
        }
        #pragma unroll
        for (int nt = 0; nt < 4; ++nt) {
            const int n = nblk + nt * 8 + g;
            const int c = ks * 8 + tig;
            uint32_t bh0 = sKh[n * QKS + c];
            uint32_t bh1 = sKh[n * QKS + c + 4];
            uint32_t bl0 = __float_as_uint(sKl[n * QKS + c]);
            uint32_t bl1 = __float_as_uint(sKl[n * QKS + c + 4]);
            #pragma unroll
            for (int mt = 0; mt < 2; ++mt) {
                MMA_TF32(acc[mt][nt][0],acc[mt][nt][1],acc[mt][nt][2],acc[mt][nt][3],
                         Ah[mt][0],Ah[mt][1],Ah[mt][2],Ah[mt][3], bh0,bh1);
                MMA_TF32(acc[mt][nt][0],acc[mt][nt][1],acc[mt][nt][2],acc[mt][nt][3],
                         Ah[mt][0],Ah[mt][1],Ah[mt][2],Ah[mt][3], bl0,bl1);
                MMA_TF32(acc[mt][nt][0],acc[mt][nt][1],acc[mt][nt][2],acc[mt][nt][3],
                         Al[mt][0],Al[mt][1],Al[mt][2],Al[mt][3], bh0,bh1);
            }
        }
    }

    float rsum[2][2] = {{0.f, 0.f}, {0.f, 0.f}};
    #pragma unroll
    for (int mt = 0; mt < 2; ++mt) {
        #pragma unroll
        for (int nt = 0; nt < 4; ++nt) {
            const int gr0 = qt * 128 + mblk + mt * 16 + g;
            const int gr1 = gr0 + 8;
            const int gc  = kt * 64 + nblk + nt * 8 + tig * 2;
            int2 m0 = *(const int2*)(M + ((size_t)b * Ss + gr0) * Ss + gc);
            int2 m1 = *(const int2*)(M + ((size_t)b * Ss + gr1) * Ss + gc);
            float2 e0 = make_float2(m0.x ? __expf(acc[mt][nt][0]) : 0.f,
                                    m0.y ? __expf(acc[mt][nt][1]) : 0.f);
            float2 e1 = make_float2(m1.x ? __expf(acc[mt][nt][2]) : 0.f,
                                    m1.y ? __expf(acc[mt][nt][3]) : 0.f);
            rsum[mt][0] += e0.x + e0.y;
            rsum[mt][1] += e1.x + e1.y;
            *(float2*)(Attn + ((size_t)bh * Ss + gr0) * Ss + gc) = e0;
            *(float2*)(Attn + ((size_t)bh * Ss + gr1) * Ss + gc) = e1;
        }
    }
    const int cidx = kt * 2 + (nblk >> 5);
    #pragma unroll
    for (int mt = 0; mt < 2; ++mt) {
        float a = rsum[mt][0];
        a += __shfl_xor_sync(0xffffffffu, a, 1);
        a += __shfl_xor_sync(0xffffffffu, a, 2);
        float c = rsum[mt][1];
        c += __shfl_xor_sync(0xffffffffu, c, 1);
        c += __shfl_xor_sync(0xffffffffu, c, 2);
        if (tig == 0) {
            const uint32_t r0 = (uint32_t)(bh * Ss + qt * 128 + mblk + mt * 16 + g);
            g_rowsum[(size_t)r0 * 32 + cidx]       = a;
            g_rowsum[(size_t)(r0 + 8) * 32 + cidx] = c;
        }
    }
}

// ============================================================================
// K_B fused v10: per-warp fragment-direct normalize + JIT dropout + attn write
// + PV.  No sP exchange; V double-buffered in smem via register staging.
// CTA: 128 q-rows x 64 d out. grid (qt=8, bh=128).
// smem: sVh[2][64*PVV] u32, sVl[2][64*PVV] f32, sInv[128]
// ============================================================================
#define PVV 72
#define VBUF (64 * PVV)
#define PV_SMEM_WORDS (2 * VBUF * 2 + 128)
#define PV_SMEM_BYTES (PV_SMEM_WORDS * 4)

extern "C" __global__ void __launch_bounds__(256, 3)
pv_kernel(float* __restrict__ Attn, const float* __restrict__ V,
          float* __restrict__ Out, uint32_t rk0, uint32_t rk1)
{
    extern __shared__ float sm[];
    uint32_t* sVh  = (uint32_t*)sm;            // [2][VBUF]
    float*    sVl  = sm + 2 * VBUF;            // [2][VBUF]
    float*    sInv = sm + 4 * VBUF;            // 128

    const int qt = blockIdx.x, bh = blockIdx.y;
    const int tid = threadIdx.x;
    const int w = tid >> 5, lane = tid & 31, g = lane >> 2, tig = lane & 3;

    float* Ag = Attn + ((size_t)bh * Ss + qt * 128) * Ss;
    const float* Vg = V + (size_t)bh * Ss * Dd;

    // deterministic row-sum reduction from qk partials
    if (tid < 128) {
        const float4* p = (const float4*)(g_rowsum +
            ((size_t)(bh * Ss + qt * 128 + tid)) * 32);
        float s = 0.f;
        #pragma unroll
        for (int jj = 0; jj < 8; ++jj) {
            float4 v = p[jj];
            s += (v.x + v.y) + (v.z + v.w);
        }
        sInv[tid] = (1.0f / 0.9f) / s;
    }

    // ---- preload V tile 0 into regs, split-store into buffer 0 ----
    float4 vst[4];
    #pragma unroll
    for (int jj = 0; jj < 4; ++jj)
        vst[jj] = ((const float4*)Vg)[tid + 256 * jj];
    #pragma unroll
    for (int jj = 0; jj < 4; ++jj) {
        int i = tid + 256 * jj;
        int row = i >> 4, c4 = (i & 15) * 4;
        uint32_t* ph = sVh + row * PVV + c4;
        float*    pl = sVl + row * PVV + c4;
        uint32_t h0 = f2tf(vst[jj].x), h1 = f2tf(vst[jj].y);
        uint32_t h2 = f2tf(vst[jj].z), h3 = f2tf(vst[jj].w);
        ph[0] = h0; ph[1] = h1; ph[2] = h2; ph[3] = h3;
        pl[0] = vst[jj].x - __uint_as_float(h0); pl[1] = vst[jj].y - __uint_as_float(h1);
        pl[2] = vst[jj].z - __uint_as_float(h2); pl[3] = vst[jj].w - __uint_as_float(h3);
    }
    __syncthreads();

    const float inv0 = sInv[w * 16 + g];
    const float inv1 = sInv[w * 16 + g + 8];
    const uint32_t rowg0 = (uint32_t)(bh * Ss + qt * 128 + w * 16 + g);
    const uint32_t rowg1 = rowg0 + 8;
    float* Ar0 = Ag + (size_t)(w * 16 + g) * Ss;
    float* Ar1 = Ag + (size_t)(w * 16 + g + 8) * Ss;

    float acc[8][4];
    #pragma unroll
    for (int nt = 0; nt < 8; ++nt)
        #pragma unroll
        for (int jj = 0; jj < 4; ++jj) acc[nt][jj] = 0.f;

    for (int kt = 0; kt < 16; ++kt) {
        const int cur = (kt & 1) * VBUF;
        const int nxt = ((kt + 1) & 1) * VBUF;

        // prefetch next V tile into regs (latency hidden under the MMA phase)
        if (kt < 15) {
            const float4* src = (const float4*)(Vg + (size_t)(kt + 1) * 64 * Dd);
            #pragma unroll
            for (int jj = 0; jj < 4; ++jj) vst[jj] = src[tid + 256 * jj];
        }

        const uint32_t* svh = sVh + cur;
        const float*    svl = sVl + cur;

        #pragma unroll
        for (int ks = 0; ks < 8; ++ks) {
            const int c0 = kt * 64 + ks * 8 + tig;
            // direct gmem fragment loads (rows partitioned per warp)
            float e0 = Ar0[c0];
            float e1 = Ar1[c0];
            float e2 = Ar0[c0 + 4];
            float e3 = Ar1[c0 + 4];
            // JIT dropout bits
            uint32_t b0 = jax_bits((rowg0 << 10) + c0,     rk0, rk1);
            uint32_t b1 = jax_bits((rowg1 << 10) + c0,     rk0, rk1);
            uint32_t b2 = jax_bits((rowg0 << 10) + c0 + 4, rk0, rk1);
            uint32_t b3 = jax_bits((rowg1 << 10) + c0 + 4, rk0, rk1);
            float w0 = (b0 < KEEP_THRESH) ? e0 * inv0 : 0.f;
            float w1 = (b1 < KEEP_THRESH) ? e1 * inv1 : 0.f;
            float w2 = (b2 < KEEP_THRESH) ? e2 * inv0 : 0.f;
            float w3 = (b3 < KEEP_THRESH) ? e3 * inv1 : 0.f;
            // final attn_weights
            Ar0[c0]     = w0;
            Ar1[c0]     = w1;
            Ar0[c0 + 4] = w2;
            Ar1[c0 + 4] = w3;
            // 3xTF32 A split
            uint32_t A0h = f2tf(w0), A1h = f2tf(w1), A2h = f2tf(w2), A3h = f2tf(w3);
            uint32_t A0l = __float_as_uint(w0 - __uint_as_float(A0h));
            uint32_t A1l = __float_as_uint(w1 - __uint_as_float(A1h));
            uint32_t A2l = __float_as_uint(w2 - __uint_as_float(A2h));
            uint32_t A3l = __float_as_uint(w3 - __uint_as_float(A3h));

            #pragma unroll
            for (int nt = 0; nt < 8; ++nt) {
                const int col = nt * 8 + g;
                uint32_t bh0 = svh[(ks * 8 + tig) * PVV + col];
                uint32_t bh1 = svh[(ks * 8 + tig + 4) * PVV + col];
                uint32_t bl0 = __float_as_uint(svl[(ks * 8 + tig) * PVV + col]);
                uint32_t bl1 = __float_as_uint(svl[(ks * 8 + tig + 4) * PVV + col]);
                MMA_TF32(acc[nt][0],acc[nt][1],acc[nt][2],acc[nt][3],
                         A0h,A1h,A2h,A3h, bh0,bh1);
                MMA_TF32(acc[nt][0],acc[nt][1],acc[nt][2],acc[nt][3],
                         A0h,A1h,A2h,A3h, bl0,bl1);
                MMA_TF32(acc[nt][0],acc[nt][1],acc[nt][2],acc[nt][3],
                         A0l,A1l,A2l,A3l, bh0,bh1);
            }
        }

        // split-store prefetched tile into the other buffer
        if (kt < 15) {
            #pragma unroll
            for (int jj = 0; jj < 4; ++jj) {
                int i = tid + 256 * jj;
                int row = i >> 4, c4 = (i & 15) * 4;
                uint32_t* ph = sVh + nxt + row * PVV + c4;
                float*    pl = sVl + nxt + row * PVV + c4;
                uint32_t h0 = f2tf(vst[jj].x), h1 = f2tf(vst[jj].y);
                uint32_t h2 = f2tf(vst[jj].z), h3 = f2tf(vst[jj].w);
                ph[0] = h0; ph[1] = h1; ph[2] = h2; ph[3] = h3;
                pl[0] = vst[jj].x - __uint_as_float(h0);
                pl[1] = vst[jj].y - __uint_as_float(h1);
                pl[2] = vst[jj].z - __uint_as_float(h2);
                pl[3] = vst[jj].w - __uint_as_float(h3);
            }
            __syncthreads();
        }
    }

    const int gr0 = qt * 128 + w * 16 + g;
    const int gr1 = gr0 + 8;
    float* Ob = Out + (size_t)bh * Ss * Dd;
    #pragma unroll
    for (int nt = 0; nt < 8; ++nt) {
        const int col = nt * 8 + tig * 2;
        *(float2*)(Ob + (size_t)gr0 * Dd + col) = make_float2(acc[nt][0], acc[nt][1]);
        *(float2*)(Ob + (size_t)gr1 * Dd + col) = make_float2(acc[nt][2], acc[nt][3]);
    }
}

// ============================================================================
extern "C" void kernel_launch(void* const* d_in, const int* in_sizes, int n_in,
                              void* d_out, int out_size) {
    const float* Q = (const float*)d_in[0];
    const float* K = (const float*)d_in[1];
    const float* V = (const float*)d_in[2];
    const int*   M = (const int*)d_in[3];

    float* out  = (float*)d_out;
    float* attn = out + (size_t)Bb * Hh * Ss * Dd;

    constexpr K2 DK = threefry_host(0u, 42u, 0u, 7u);

    cudaFuncSetAttribute(qk_kernel, cudaFuncAttributeMaxDynamicSharedMemorySize,
                         QK_SMEM_BYTES);
    cudaFuncSetAttribute(pv_kernel, cudaFuncAttributeMaxDynamicSharedMemorySize,
                         PV_SMEM_BYTES);

    qk_kernel<<<dim3(16, 8, 128), 256, QK_SMEM_BYTES>>>(Q, K, M, attn);
    pv_kernel<<<dim3(8, 128), 256, PV_SMEM_BYTES>>>(attn, V, out, DK.a, DK.b);
}

// round 11
// speedup vs baseline: 2.7815x; 2.7815x over previous
#include <cuda_runtime.h>
#include <cstdint>

// Problem constants: B=8, H=16, S=1024, D=64.
#define Bb 8
#define Hh 16
#define Ss 1024
#define Dd 64

struct K2 { uint32_t a, b; };

__host__ __device__ constexpr uint32_t rotl_c(uint32_t x, int r) {
    return (x << r) | (x >> (32 - r));
}

constexpr K2 threefry_host(uint32_t k0, uint32_t k1, uint32_t c0, uint32_t c1) {
    uint32_t ks[3] = { k0, k1, 0x1BD11BDAu ^ k0 ^ k1 };
    uint32_t x0 = c0 + ks[0], x1 = c1 + ks[1];
    const int rot[8] = {13, 15, 26, 6, 17, 29, 16, 24};
    for (int g = 0; g < 5; ++g) {
        for (int i = 0; i < 4; ++i) {
            x0 += x1;
            x1 = rotl_c(x1, rot[(g & 1) * 4 + i]);
            x1 ^= x0;
        }
        x0 += ks[(g + 1) % 3];
        x1 += ks[(g + 2) % 3] + (uint32_t)(g + 1);
    }
    return { x0, x1 };
}

// JAX partitionable threefry: counter (0, idx), bits = x0 ^ x1
__device__ __forceinline__ uint32_t jax_bits(uint32_t idx, uint32_t k0, uint32_t k1) {
    const uint32_t ks2 = 0x1BD11BDAu ^ k0 ^ k1;
    uint32_t x0 = k0;
    uint32_t x1 = idx + k1;
#define TF_RND(r) { x0 += x1; x1 = __funnelshift_l(x1, x1, (r)); x1 ^= x0; }
    TF_RND(13) TF_RND(15) TF_RND(26) TF_RND(6)   x0 += k1;  x1 += ks2 + 1u;
    TF_RND(17) TF_RND(29) TF_RND(16) TF_RND(24)  x0 += ks2; x1 += k0 + 2u;
    TF_RND(13) TF_RND(15) TF_RND(26) TF_RND(6)   x0 += k0;  x1 += k1 + 3u;
    TF_RND(17) TF_RND(29) TF_RND(16) TF_RND(24)  x0 += k1;  x1 += ks2 + 4u;
    TF_RND(13) TF_RND(15) TF_RND(26) TF_RND(6)   x0 += ks2; x1 += k0 + 5u;
#undef TF_RND
    return x0 ^ x1;
}
// keep iff uniform(bits) < 0.9f  ⟺  bits < 0xE6666600
#define KEEP_THRESH 0xE6666600u

__device__ __forceinline__ uint32_t f2tf(float x) {
    uint32_t r;
    asm("cvt.rna.tf32.f32 %0, %1;" : "=r"(r) : "f"(x));
    return r;
}

#define MMA_TF32(d0,d1,d2,d3,a0,a1,a2,a3,b0,b1)                               \
    asm volatile("mma.sync.aligned.m16n8k8.row.col.f32.tf32.tf32.f32 "        \
                 "{%0,%1,%2,%3},{%4,%5,%6,%7},{%8,%9},{%0,%1,%2,%3};"         \
                 : "+f"(d0), "+f"(d1), "+f"(d2), "+f"(d3)                     \
                 : "r"(a0), "r"(a1), "r"(a2), "r"(a3), "r"(b0), "r"(b1))

// per-row 1/(0.9*sum) for the normalize epilogue
__device__ float g_inv[(size_t)Bb * Hh * Ss];

// ============================================================================
// Fused attention kernel. CTA: 64 q-rows x all 1024 keys -> 64x64 out.
// grid (qt=16, bh=128). 8 warps: mw = w&3 (16-row block), nh = w>>2 (n-half).
// Per kt (64-key tile): K->smem, QK mma, {mask,exp,rowsum,threefry,store a},
//                       V->smem, PV mma accumulate (unnormalized).
// End: rowsum -> inv, O = O'*inv, g_inv written. attn holds a (unnormalized);
//      norm_kernel scales it by inv afterwards.
// smem words: sQ 64*68 | sKh 64*68 | sKl 64*68 | sEx 64*68 | sRow 128 | sInv 64
// ============================================================================
#define STR 68
#define SMW (4 * 64 * STR + 128 + 64)
#define SMEM_BYTES (SMW * 4)

extern "C" __global__ void __launch_bounds__(256, 2)
attn_fused_kernel(const float* __restrict__ Q, const float* __restrict__ K,
                  const float* __restrict__ V, const int* __restrict__ M,
                  float* __restrict__ Attn, float* __restrict__ Out,
                  uint32_t rk0, uint32_t rk1)
{
    extern __shared__ float sm[];
    float*    sQ   = sm;                         // 64*68
    uint32_t* sKh  = (uint32_t*)(sm + 64 * STR); // 64*68 (K hi / V hi)
    float*    sKl  = sm + 2 * 64 * STR;          // 64*68 (K lo / V lo)
    float*    sEx  = sm + 3 * 64 * STR;          // 64*68 (P exchange)
    float*    sRow = sm + 4 * 64 * STR;          // 128
    float*    sInv = sRow + 128;                 // 64

    const int qt = blockIdx.x, bh = blockIdx.y;
    const int b  = bh >> 4;
    const int tid = threadIdx.x;
    const int w = tid >> 5, lane = tid & 31, g = lane >> 2, tig = lane & 3;
    const int mw = w & 3, nh = w >> 2;

    const float* Qg = Q + ((size_t)bh * Ss + qt * 64) * Dd;
    const float* Kg = K + (size_t)bh * Ss * Dd;
    const float* Vg = V + (size_t)bh * Ss * Dd;

    // load Q tile (64x64), prescaled by 1/sqrt(64)
    for (int i = tid; i < 64 * 16; i += 256) {
        int row = i >> 4, c4 = (i & 15) * 4;
        float4 v = ((const float4*)Qg)[i];
        float* p = sQ + row * STR + c4;
        p[0] = v.x * 0.125f; p[1] = v.y * 0.125f;
        p[2] = v.z * 0.125f; p[3] = v.w * 0.125f;
    }

    const int r0l = mw * 16 + g;        // local row of C rows g / g+8
    const int r1l = r0l + 8;
    const int gr0 = qt * 64 + r0l;      // row within [Ss]
    const int gr1 = gr0 + 8;
    float* Ar0 = Attn + ((size_t)bh * Ss + gr0) * Ss;
    float* Ar1 = Attn + ((size_t)bh * Ss + gr1) * Ss;
    const int* Mr0 = M + ((size_t)b * Ss + gr0) * Ss;
    const int* Mr1 = M + ((size_t)b * Ss + gr1) * Ss;
    const uint32_t ib0 = ((uint32_t)(bh * Ss + gr0)) << 10;
    const uint32_t ib1 = ((uint32_t)(bh * Ss + gr1)) << 10;

    float oacc[4][4];
    #pragma unroll
    for (int nt = 0; nt < 4; ++nt)
        #pragma unroll
        for (int j = 0; j < 4; ++j) oacc[nt][j] = 0.f;
    float rsum0 = 0.f, rsum1 = 0.f;

    for (int kt = 0; kt < 16; ++kt) {
        __syncthreads();   // prev PV reads of sKh/sKl + prev sEx reads done
        // ---- load K tile (64 keys x 64 d), hi/lo split ----
        {
            const float4* src = (const float4*)(Kg + (size_t)kt * 64 * Dd);
            for (int i = tid; i < 64 * 16; i += 256) {
                int row = i >> 4, c4 = (i & 15) * 4;
                float4 v = src[i];
                uint32_t* ph = sKh + row * STR + c4;
                float*    pl = sKl + row * STR + c4;
                uint32_t h0 = f2tf(v.x), h1 = f2tf(v.y), h2 = f2tf(v.z), h3 = f2tf(v.w);
                ph[0] = h0; ph[1] = h1; ph[2] = h2; ph[3] = h3;
                pl[0] = v.x - __uint_as_float(h0); pl[1] = v.y - __uint_as_float(h1);
                pl[2] = v.z - __uint_as_float(h2); pl[3] = v.w - __uint_as_float(h3);
            }
        }
        __syncthreads();

        // ---- QK: S = Q K^T (3xTF32) ----
        float sacc[4][4];
        #pragma unroll
        for (int nt = 0; nt < 4; ++nt)
            #pragma unroll
            for (int j = 0; j < 4; ++j) sacc[nt][j] = 0.f;

        #pragma unroll
        for (int ks = 0; ks < 8; ++ks) {
            const int c = ks * 8 + tig;
            float v0 = sQ[r0l * STR + c];
            float v1 = sQ[r1l * STR + c];
            float v2 = sQ[r0l * STR + c + 4];
            float v3 = sQ[r1l * STR + c + 4];
            uint32_t Ah0 = f2tf(v0), Ah1 = f2tf(v1), Ah2 = f2tf(v2), Ah3 = f2tf(v3);
            uint32_t Al0 = __float_as_uint(v0 - __uint_as_float(Ah0));
            uint32_t Al1 = __float_as_uint(v1 - __uint_as_float(Ah1));
            uint32_t Al2 = __float_as_uint(v2 - __uint_as_float(Ah2));
            uint32_t Al3 = __float_as_uint(v3 - __uint_as_float(Ah3));
            #pragma unroll
            for (int nt = 0; nt < 4; ++nt) {
                const int n = nh * 32 + nt * 8 + g;
                uint32_t bh0 = sKh[n * STR + c];
                uint32_t bh1 = sKh[n * STR + c + 4];
                uint32_t bl0 = __float_as_uint(sKl[n * STR + c]);
                uint32_t bl1 = __float_as_uint(sKl[n * STR + c + 4]);
                MMA_TF32(sacc[nt][0],sacc[nt][1],sacc[nt][2],sacc[nt][3],
                         Ah0,Ah1,Ah2,Ah3, bh0,bh1);
                MMA_TF32(sacc[nt][0],sacc[nt][1],sacc[nt][2],sacc[nt][3],
                         Ah0,Ah1,Ah2,Ah3, bl0,bl1);
                MMA_TF32(sacc[nt][0],sacc[nt][1],sacc[nt][2],sacc[nt][3],
                         Al0,Al1,Al2,Al3, bh0,bh1);
            }
        }

        // ---- epilogue: mask -> exp -> rowsum -> dropout -> a stores ----
        #pragma unroll
        for (int nt = 0; nt < 4; ++nt) {
            const int gc = kt * 64 + nh * 32 + nt * 8 + tig * 2;
            int2 m0 = *(const int2*)(Mr0 + gc);
            int2 m1 = *(const int2*)(Mr1 + gc);
            float e00 = m0.x ? __expf(sacc[nt][0]) : 0.f;
            float e01 = m0.y ? __expf(sacc[nt][1]) : 0.f;
            float e10 = m1.x ? __expf(sacc[nt][2]) : 0.f;
            float e11 = m1.y ? __expf(sacc[nt][3]) : 0.f;
            rsum0 += e00 + e01;
            rsum1 += e10 + e11;
            uint32_t b00 = jax_bits(ib0 + gc,     rk0, rk1);
            uint32_t b01 = jax_bits(ib0 + gc + 1, rk0, rk1);
            uint32_t b10 = jax_bits(ib1 + gc,     rk0, rk1);
            uint32_t b11 = jax_bits(ib1 + gc + 1, rk0, rk1);
            float a00 = (b00 < KEEP_THRESH) ? e00 : 0.f;
            float a01 = (b01 < KEEP_THRESH) ? e01 : 0.f;
            float a10 = (b10 < KEEP_THRESH) ? e10 : 0.f;
            float a11 = (b11 < KEEP_THRESH) ? e11 : 0.f;
            *(float2*)(Ar0 + gc) = make_float2(a00, a01);
            *(float2*)(Ar1 + gc) = make_float2(a10, a11);
            const int cl = nh * 32 + nt * 8 + tig * 2;
            *(float2*)(sEx + r0l * STR + cl) = make_float2(a00, a01);
            *(float2*)(sEx + r1l * STR + cl) = make_float2(a10, a11);
        }
        __syncthreads();   // sEx complete; K reads done -> V may overwrite

        // ---- load V tile (64 keys x 64 d), hi/lo split ----
        {
            const float4* src = (const float4*)(Vg + (size_t)kt * 64 * Dd);
            for (int i = tid; i < 64 * 16; i += 256) {
                int row = i >> 4, c4 = (i & 15) * 4;
                float4 v = src[i];
                uint32_t* ph = sKh + row * STR + c4;
                float*    pl = sKl + row * STR + c4;
                uint32_t h0 = f2tf(v.x), h1 = f2tf(v.y), h2 = f2tf(v.z), h3 = f2tf(v.w);
                ph[0] = h0; ph[1] = h1; ph[2] = h2; ph[3] = h3;
                pl[0] = v.x - __uint_as_float(h0); pl[1] = v.y - __uint_as_float(h1);
                pl[2] = v.z - __uint_as_float(h2); pl[3] = v.w - __uint_as_float(h3);
            }
        }
        __syncthreads();

        // ---- PV: O' += a @ V (3xTF32) ----
        #pragma unroll
        for (int ks = 0; ks < 8; ++ks) {
            const int c = ks * 8 + tig;
            float w0 = sEx[r0l * STR + c];
            float w1 = sEx[r1l * STR + c];
            float w2 = sEx[r0l * STR + c + 4];
            float w3 = sEx[r1l * STR + c + 4];
            uint32_t Ah0 = f2tf(w0), Ah1 = f2tf(w1), Ah2 = f2tf(w2), Ah3 = f2tf(w3);
            uint32_t Al0 = __float_as_uint(w0 - __uint_as_float(Ah0));
            uint32_t Al1 = __float_as_uint(w1 - __uint_as_float(Ah1));
            uint32_t Al2 = __float_as_uint(w2 - __uint_as_float(Ah2));
            uint32_t Al3 = __float_as_uint(w3 - __uint_as_float(Ah3));
            #pragma unroll
            for (int nt = 0; nt < 4; ++nt) {
                const int col = nh * 32 + nt * 8 + g;
                uint32_t bh0 = sKh[(ks * 8 + tig) * STR + col];
                uint32_t bh1 = sKh[(ks * 8 + tig + 4) * STR + col];
                uint32_t bl0 = __float_as_uint(sKl[(ks * 8 + tig) * STR + col]);
                uint32_t bl1 = __float_as_uint(sKl[(ks * 8 + tig + 4) * STR + col]);
                MMA_TF32(oacc[nt][0],oacc[nt][1],oacc[nt][2],oacc[nt][3],
                         Ah0,Ah1,Ah2,Ah3, bh0,bh1);
                MMA_TF32(oacc[nt][0],oacc[nt][1],oacc[nt][2],oacc[nt][3],
                         Ah0,Ah1,Ah2,Ah3, bl0,bl1);
                MMA_TF32(oacc[nt][0],oacc[nt][1],oacc[nt][2],oacc[nt][3],
                         Al0,Al1,Al2,Al3, bh0,bh1);
            }
        }
    }

    // ---- rowsum -> inv ----
    rsum0 += __shfl_xor_sync(0xffffffffu, rsum0, 1);
    rsum0 += __shfl_xor_sync(0xffffffffu, rsum0, 2);
    rsum1 += __shfl_xor_sync(0xffffffffu, rsum1, 1);
    rsum1 += __shfl_xor_sync(0xffffffffu, rsum1, 2);
    if (tig == 0) {
        sRow[r0l * 2 + nh] = rsum0;
        sRow[r1l * 2 + nh] = rsum1;
    }
    __syncthreads();
    if (tid < 64) {
        float inv = (1.0f / 0.9f) / (sRow[tid * 2] + sRow[tid * 2 + 1]);
        sInv[tid] = inv;
        g_inv[(size_t)bh * Ss + qt * 64 + tid] = inv;
    }
    __syncthreads();

    // ---- store O = O' * inv ----
    const float inv0 = sInv[r0l];
    const float inv1 = sInv[r1l];
    float* Ob = Out + (size_t)bh * Ss * Dd;
    #pragma unroll
    for (int nt = 0; nt < 4; ++nt) {
        const int col = nh * 32 + nt * 8 + tig * 2;
        *(float2*)(Ob + (size_t)gr0 * Dd + col) =
            make_float2(oacc[nt][0] * inv0, oacc[nt][1] * inv0);
        *(float2*)(Ob + (size_t)gr1 * Dd + col) =
            make_float2(oacc[nt][2] * inv1, oacc[nt][3] * inv1);
    }
}

// ============================================================================
// Normalize epilogue: attn[row][*] *= g_inv[row]   (a -> final weights)
// ============================================================================
extern "C" __global__ void __launch_bounds__(256)
norm_kernel(float* __restrict__ Attn)
{
    size_t i = (size_t)blockIdx.x * 256 + threadIdx.x;  // float4 index
    const float inv = g_inv[i >> 8];                    // 256 float4 per row
    float4* p = (float4*)Attn + i;
    float4 v = *p;
    v.x *= inv; v.y *= inv; v.z *= inv; v.w *= inv;
    *p = v;
}

// ============================================================================
extern "C" void kernel_launch(void* const* d_in, const int* in_sizes, int n_in,
                              void* d_out, int out_size) {
    const float* Q = (const float*)d_in[0];
    const float* K = (const float*)d_in[1];
    const float* V = (const float*)d_in[2];
    const int*   M = (const int*)d_in[3];

    float* out  = (float*)d_out;
    float* attn = out + (size_t)Bb * Hh * Ss * Dd;

    constexpr K2 DK = threefry_host(0u, 42u, 0u, 7u);

    cudaFuncSetAttribute(attn_fused_kernel,
                         cudaFuncAttributeMaxDynamicSharedMemorySize, SMEM_BYTES);

    attn_fused_kernel<<<dim3(16, 128), 256, SMEM_BYTES>>>(
        Q, K, V, M, attn, out, DK.a, DK.b);

    const int n4 = (Bb * Hh * Ss * (Ss / 4)) / 256;   // 131072 CTAs
    norm_kernel<<<n4, 256>>>(attn);
}

// round 12
// speedup vs baseline: 3.6382x; 1.3080x over previous
#include <cuda_runtime.h>
#include <cstdint>

// Problem constants: B=8, H=16, S=1024, D=64.
#define Bb 8
#define Hh 16
#define Ss 1024
#define Dd 64

struct K2 { uint32_t a, b; };

__host__ __device__ constexpr uint32_t rotl_c(uint32_t x, int r) {
    return (x << r) | (x >> (32 - r));
}

constexpr K2 threefry_host(uint32_t k0, uint32_t k1, uint32_t c0, uint32_t c1) {
    uint32_t ks[3] = { k0, k1, 0x1BD11BDAu ^ k0 ^ k1 };
    uint32_t x0 = c0 + ks[0], x1 = c1 + ks[1];
    const int rot[8] = {13, 15, 26, 6, 17, 29, 16, 24};
    for (int g = 0; g < 5; ++g) {
        for (int i = 0; i < 4; ++i) {
            x0 += x1;
            x1 = rotl_c(x1, rot[(g & 1) * 4 + i]);
            x1 ^= x0;
        }
        x0 += ks[(g + 1) % 3];
        x1 += ks[(g + 2) % 3] + (uint32_t)(g + 1);
    }
    return { x0, x1 };
}

// JAX partitionable threefry: counter (0, idx), bits = x0 ^ x1
__device__ __forceinline__ uint32_t jax_bits(uint32_t idx, uint32_t k0, uint32_t k1) {
    const uint32_t ks2 = 0x1BD11BDAu ^ k0 ^ k1;
    uint32_t x0 = k0;
    uint32_t x1 = idx + k1;
#define TF_RND(r) { x0 += x1; x1 = __funnelshift_l(x1, x1, (r)); x1 ^= x0; }
    TF_RND(13) TF_RND(15) TF_RND(26) TF_RND(6)   x0 += k1;  x1 += ks2 + 1u;
    TF_RND(17) TF_RND(29) TF_RND(16) TF_RND(24)  x0 += ks2; x1 += k0 + 2u;
    TF_RND(13) TF_RND(15) TF_RND(26) TF_RND(6)   x0 += k0;  x1 += k1 + 3u;
    TF_RND(17) TF_RND(29) TF_RND(16) TF_RND(24)  x0 += k1;  x1 += ks2 + 4u;
    TF_RND(13) TF_RND(15) TF_RND(26) TF_RND(6)   x0 += ks2; x1 += k0 + 5u;
#undef TF_RND
    return x0 ^ x1;
}
// keep iff uniform(bits) < 0.9f  ⟺  bits < 0xE6666600
#define KEEP_THRESH 0xE6666600u

__device__ __forceinline__ uint32_t f2tf(float x) {
    uint32_t r;
    asm("cvt.rna.tf32.f32 %0, %1;" : "=r"(r) : "f"(x));
    return r;
}

#define MMA_TF32(d0,d1,d2,d3,a0,a1,a2,a3,b0,b1)                               \
    asm volatile("mma.sync.aligned.m16n8k8.row.col.f32.tf32.tf32.f32 "        \
                 "{%0,%1,%2,%3},{%4,%5,%6,%7},{%8,%9},{%0,%1,%2,%3};"         \
                 : "+f"(d0), "+f"(d1), "+f"(d2), "+f"(d3)                     \
                 : "r"(a0), "r"(a1), "r"(a2), "r"(a3), "r"(b0), "r"(b1))

// per-row exp-sum partials: [B*H*S rows][32 col-blocks of 32]
__device__ float g_rowsum[(size_t)Bb * Hh * Ss * 32];

// ============================================================================
// K_A: e = mask ? exp((Q K^T)/8) : 0  -> Attn buffer, + partial exp-sums.
// (proven R8 version, unchanged)
// ============================================================================
#define QKS 68
#define QK_SMEM_BYTES ((128 * QKS + 2 * 64 * QKS) * 4)

extern "C" __global__ void __launch_bounds__(256)
qk_kernel(const float* __restrict__ Q, const float* __restrict__ K,
          const int* __restrict__ M, float* __restrict__ Attn)
{
    extern __shared__ float sm[];
    float*    sQ  = sm;
    uint32_t* sKh = (uint32_t*)(sm + 128 * QKS);
    float*    sKl = (float*)(sKh + 64 * QKS);

    const int kt = blockIdx.x, qt = blockIdx.y, bh = blockIdx.z;
    const int b  = bh >> 4;
    const int tid = threadIdx.x;
    const int w = tid >> 5, lane = tid & 31, g = lane >> 2, tig = lane & 3;

    const float* Qg = Q + ((size_t)bh * Ss + qt * 128) * Dd;
    const float* Kg = K + ((size_t)bh * Ss + kt * 64) * Dd;

    for (int i = tid; i < 128 * 16; i += 256) {
        int row = i >> 4, c4 = (i & 15) * 4;
        float4 v = ((const float4*)Qg)[i];
        float* p = sQ + row * QKS + c4;
        p[0] = v.x * 0.125f; p[1] = v.y * 0.125f;
        p[2] = v.z * 0.125f; p[3] = v.w * 0.125f;
    }
    for (int i = tid; i < 64 * 16; i += 256) {
        int row = i >> 4, c4 = (i & 15) * 4;
        float4 v = ((const float4*)Kg)[i];
        uint32_t* ph = sKh + row * QKS + c4;
        float*    pl = sKl + row * QKS + c4;
        uint32_t h0 = f2tf(v.x), h1 = f2tf(v.y), h2 = f2tf(v.z), h3 = f2tf(v.w);
        ph[0] = h0; ph[1] = h1; ph[2] = h2; ph[3] = h3;
        pl[0] = v.x - __uint_as_float(h0); pl[1] = v.y - __uint_as_float(h1);
        pl[2] = v.z - __uint_as_float(h2); pl[3] = v.w - __uint_as_float(h3);
    }
    __syncthreads();

    const int mblk = (w & 3) * 32;
    const int nblk = (w >> 2) * 32;

    float acc[2][4][4];
    #pragma unroll
    for (int mt = 0; mt < 2; ++mt)
        #pragma unroll
        for (int nt = 0; nt < 4; ++nt)
            #pragma unroll
            for (int j = 0; j < 4; ++j) acc[mt][nt][j] = 0.f;

    #pragma unroll
    for (int ks = 0; ks < 8; ++ks) {
        uint32_t Ah[2][4], Al[2][4];
        #pragma unroll
        for (int mt = 0; mt < 2; ++mt) {
            const int r = mblk + mt * 16;
            const int c = ks * 8 + tig;
            float v0 = sQ[(r + g) * QKS + c];
            float v1 = sQ[(r + g + 8) * QKS + c];
            float v2 = sQ[(r + g) * QKS + c + 4];
            float v3 = sQ[(r + g + 8) * QKS + c + 4];
            Ah[mt][0] = f2tf(v0); Al[mt][0] = __float_as_uint(v0 - __uint_as_float(Ah[mt][0]));
            Ah[mt][1] = f2tf(v1); Al[mt][1] = __float_as_uint(v1 - __uint_as_float(Ah[mt][1]));
            Ah[mt][2] = f2tf(v2); Al[mt][2] = __float_as_uint(v2 - __uint_as_float(Ah[mt][2]));
            Ah[mt][3] = f2tf(v3); Al[mt][3] = __float_as_uint(v3 - __uint_as_float(Ah[mt][3]));
        }
        #pragma unroll
        for (int nt = 0; nt < 4; ++nt) {
            const int n = nblk + nt * 8 + g;
            const int c = ks * 8 + tig;
            uint32_t bh0 = sKh[n * QKS + c];
            uint32_t bh1 = sKh[n * QKS + c + 4];
            uint32_t bl0 = __float_as_uint(sKl[n * QKS + c]);
            uint32_t bl1 = __float_as_uint(sKl[n * QKS + c + 4]);
            #pragma unroll
            for (int mt = 0; mt < 2; ++mt) {
                MMA_TF32(acc[mt][nt][0],acc[mt][nt][1],acc[mt][nt][2],acc[mt][nt][3],
                         Ah[mt][0],Ah[mt][1],Ah[mt][2],Ah[mt][3], bh0,bh1);
                MMA_TF32(acc[mt][nt][0],acc[mt][nt][1],acc[mt][nt][2],acc[mt][nt][3],
                         Ah[mt][0],Ah[mt][1],Ah[mt][2],Ah[mt][3], bl0,bl1);
                MMA_TF32(acc[mt][nt][0],acc[mt][nt][1],acc[mt][nt][2],acc[mt][nt][3],
                         Al[mt][0],Al[mt][1],Al[mt][2],Al[mt][3], bh0,bh1);
            }
        }
    }

    float rsum[2][2] = {{0.f, 0.f}, {0.f, 0.f}};
    #pragma unroll
    for (int mt = 0; mt < 2; ++mt) {
        #pragma unroll
        for (int nt = 0; nt < 4; ++nt) {
            const int gr0 = qt * 128 + mblk + mt * 16 + g;
            const int gr1 = gr0 + 8;
            const int gc  = kt * 64 + nblk + nt * 8 + tig * 2;
            int2 m0 = *(const int2*)(M + ((size_t)b * Ss + gr0) * Ss + gc);
            int2 m1 = *(const int2*)(M + ((size_t)b * Ss + gr1) * Ss + gc);
            float2 e0 = make_float2(m0.x ? __expf(acc[mt][nt][0]) : 0.f,
                                    m0.y ? __expf(acc[mt][nt][1]) : 0.f);
            float2 e1 = make_float2(m1.x ? __expf(acc[mt][nt][2]) : 0.f,
                                    m1.y ? __expf(acc[mt][nt][3]) : 0.f);
            rsum[mt][0] += e0.x + e0.y;
            rsum[mt][1] += e1.x + e1.y;
            *(float2*)(Attn + ((size_t)bh * Ss + gr0) * Ss + gc) = e0;
            *(float2*)(Attn + ((size_t)bh * Ss + gr1) * Ss + gc) = e1;
        }
    }
    const int cidx = kt * 2 + (nblk >> 5);
    #pragma unroll
    for (int mt = 0; mt < 2; ++mt) {
        float a = rsum[mt][0];
        a += __shfl_xor_sync(0xffffffffu, a, 1);
        a += __shfl_xor_sync(0xffffffffu, a, 2);
        float c = rsum[mt][1];
        c += __shfl_xor_sync(0xffffffffu, c, 1);
        c += __shfl_xor_sync(0xffffffffu, c, 2);
        if (tig == 0) {
            const uint32_t r0 = (uint32_t)(bh * Ss + qt * 128 + mblk + mt * 16 + g);
            g_rowsum[(size_t)r0 * 32 + cidx]       = a;
            g_rowsum[(size_t)(r0 + 8) * 32 + cidx] = c;
        }
    }
}

// ============================================================================
// K_B v12: warp-private dropout->sP (no CTA barrier between threefry and MMA),
// V double-buffered via register staging, ONE __syncthreads per kt.
// CTA: 128 q-rows x 64 d out. grid (qt=8, bh=128). Warp w owns rows 16w..16w+15.
// smem: sP[128*PVS] | sVh[2][64*PVS] | sVl[2][64*PVS] | sInv[128]
// ============================================================================
#define PVS 68
#define VB (64 * PVS)
#define PV_SMEM_WORDS (128 * PVS + 4 * VB + 128)
#define PV_SMEM_BYTES (PV_SMEM_WORDS * 4)

extern "C" __global__ void __launch_bounds__(256, 2)
pv_kernel(float* __restrict__ Attn, const float* __restrict__ V,
          float* __restrict__ Out, uint32_t rk0, uint32_t rk1)
{
    extern __shared__ float sm[];
    float*    sP   = sm;                         // 128*68 (warp-private rows)
    uint32_t* sVh  = (uint32_t*)(sm + 128 * PVS);// [2][VB]
    float*    sVl  = sm + 128 * PVS + 2 * VB;    // [2][VB]
    float*    sInv = sm + 128 * PVS + 4 * VB;    // 128

    const int qt = blockIdx.x, bh = blockIdx.y;
    const int tid = threadIdx.x;
    const int w = tid >> 5, lane = tid & 31, g = lane >> 2, tig = lane & 3;

    float* Ag = Attn + ((size_t)bh * Ss + qt * 128) * Ss;
    const float* Vg = V + (size_t)bh * Ss * Dd;

    // deterministic row-sum reduction from qk partials
    if (tid < 128) {
        const float4* p = (const float4*)(g_rowsum +
            ((size_t)(bh * Ss + qt * 128 + tid)) * 32);
        float s = 0.f;
        #pragma unroll
        for (int jj = 0; jj < 8; ++jj) {
            float4 v = p[jj];
            s += (v.x + v.y) + (v.z + v.w);
        }
        sInv[tid] = (1.0f / 0.9f) / s;
    }

    // preload V tile 0 -> regs -> buffer 0 (hi/lo split)
    float4 vst[4];
    #pragma unroll
    for (int jj = 0; jj < 4; ++jj)
        vst[jj] = ((const float4*)Vg)[tid + 256 * jj];
    #pragma unroll
    for (int jj = 0; jj < 4; ++jj) {
        int i = tid + 256 * jj;
        int row = i >> 4, c4 = (i & 15) * 4;
        uint32_t* ph = sVh + row * PVS + c4;
        float*    pl = sVl + row * PVS + c4;
        uint32_t h0 = f2tf(vst[jj].x), h1 = f2tf(vst[jj].y);
        uint32_t h2 = f2tf(vst[jj].z), h3 = f2tf(vst[jj].w);
        ph[0] = h0; ph[1] = h1; ph[2] = h2; ph[3] = h3;
        pl[0] = vst[jj].x - __uint_as_float(h0); pl[1] = vst[jj].y - __uint_as_float(h1);
        pl[2] = vst[jj].z - __uint_as_float(h2); pl[3] = vst[jj].w - __uint_as_float(h3);
    }
    __syncthreads();   // sInv + V0 visible

    const int r0l = w * 16 + g;       // MMA fragment rows (warp-private)
    const int r1l = r0l + 8;
    // dropout-loop lane mapping: rows w*16 + 2*jj + (lane>>4), cols (lane&15)*4
    const int drow = (lane >> 4);
    const int dcol = (lane & 15) * 4;

    float acc[8][4];
    #pragma unroll
    for (int nt = 0; nt < 8; ++nt)
        #pragma unroll
        for (int jj = 0; jj < 4; ++jj) acc[nt][jj] = 0.f;

    for (int kt = 0; kt < 16; ++kt) {
        const int cur = (kt & 1) * VB;
        const int nxt = ((kt + 1) & 1) * VB;

        // ---- warp-private dropout: own 16 rows, cols of tile kt ----
        #pragma unroll
        for (int jj = 0; jj < 8; ++jj) {
            const int lrow = w * 16 + jj * 2 + drow;
            const int col  = kt * 64 + dcol;
            float* gp = Ag + (size_t)lrow * Ss + col;
            float4 v = *(const float4*)gp;
            const float inv = sInv[lrow];
            const uint32_t idx0 =
                ((uint32_t)(bh * Ss + qt * 128 + lrow) << 10) + col;
            uint32_t b0 = jax_bits(idx0 + 0, rk0, rk1);
            uint32_t b1 = jax_bits(idx0 + 1, rk0, rk1);
            uint32_t b2 = jax_bits(idx0 + 2, rk0, rk1);
            uint32_t b3 = jax_bits(idx0 + 3, rk0, rk1);
            v.x = (b0 < KEEP_THRESH) ? v.x * inv : 0.f;
            v.y = (b1 < KEEP_THRESH) ? v.y * inv : 0.f;
            v.z = (b2 < KEEP_THRESH) ? v.z * inv : 0.f;
            v.w = (b3 < KEEP_THRESH) ? v.w * inv : 0.f;
            *(float4*)gp = v;                                 // final weights
            *(float4*)(sP + lrow * PVS + dcol) = v;           // own-warp region
        }
        __syncwarp();   // sP rows are warp-private: warp-level sync suffices

        // ---- prefetch next V tile into regs (hidden under MMA) ----
        if (kt < 15) {
            const float4* src = (const float4*)(Vg + (size_t)(kt + 1) * 64 * Dd);
            #pragma unroll
            for (int jj = 0; jj < 4; ++jj) vst[jj] = src[tid + 256 * jj];
        }

        // ---- PV MMA: A from own sP rows, B from current V buffer ----
        const uint32_t* svh = sVh + cur;
        const float*    svl = sVl + cur;
        #pragma unroll
        for (int ks = 0; ks < 8; ++ks) {
            const int c = ks * 8 + tig;
            float w0 = sP[r0l * PVS + c];
            float w1 = sP[r1l * PVS + c];
            float w2 = sP[r0l * PVS + c + 4];
            float w3 = sP[r1l * PVS + c + 4];
            uint32_t Ah0 = f2tf(w0), Ah1 = f2tf(w1), Ah2 = f2tf(w2), Ah3 = f2tf(w3);
            uint32_t Al0 = __float_as_uint(w0 - __uint_as_float(Ah0));
            uint32_t Al1 = __float_as_uint(w1 - __uint_as_float(Ah1));
            uint32_t Al2 = __float_as_uint(w2 - __uint_as_float(Ah2));
            uint32_t Al3 = __float_as_uint(w3 - __uint_as_float(Ah3));
            #pragma unroll
            for (int nt = 0; nt < 8; ++nt) {
                const int col = nt * 8 + g;
                uint32_t bh0 = svh[(ks * 8 + tig) * PVS + col];
                uint32_t bh1 = svh[(ks * 8 + tig + 4) * PVS + col];
                uint32_t bl0 = __float_as_uint(svl[(ks * 8 + tig) * PVS + col]);
                uint32_t bl1 = __float_as_uint(svl[(ks * 8 + tig + 4) * PVS + col]);
                MMA_TF32(acc[nt][0],acc[nt][1],acc[nt][2],acc[nt][3],
                         Ah0,Ah1,Ah2,Ah3, bh0,bh1);
                MMA_TF32(acc[nt][0],acc[nt][1],acc[nt][2],acc[nt][3],
                         Ah0,Ah1,Ah2,Ah3, bl0,bl1);
                MMA_TF32(acc[nt][0],acc[nt][1],acc[nt][2],acc[nt][3],
                         Al0,Al1,Al2,Al3, bh0,bh1);
            }
        }

        // ---- split-store prefetched V into the other buffer ----
        if (kt < 15) {
            #pragma unroll
            for (int jj = 0; jj < 4; ++jj) {
                int i = tid + 256 * jj;
                int row = i >> 4, c4 = (i & 15) * 4;
                uint32_t* ph = sVh + nxt + row * PVS + c4;
                float*    pl = sVl + nxt + row * PVS + c4;
                uint32_t h0 = f2tf(vst[jj].x), h1 = f2tf(vst[jj].y);
                uint32_t h2 = f2tf(vst[jj].z), h3 = f2tf(vst[jj].w);
                ph[0] = h0; ph[1] = h1; ph[2] = h2; ph[3] = h3;
                pl[0] = vst[jj].x - __uint_as_float(h0);
                pl[1] = vst[jj].y - __uint_as_float(h1);
                pl[2] = vst[jj].z - __uint_as_float(h2);
                pl[3] = vst[jj].w - __uint_as_float(h3);
            }
            __syncthreads();   // V(next) ready; V(cur) reads complete
        }
    }

    const int gr0 = qt * 128 + w * 16 + g;
    const int gr1 = gr0 + 8;
    float* Ob = Out + (size_t)bh * Ss * Dd;
    #pragma unroll
    for (int nt = 0; nt < 8; ++nt) {
        const int col = nt * 8 + tig * 2;
        *(float2*)(Ob + (size_t)gr0 * Dd + col) = make_float2(acc[nt][0], acc[nt][1]);
        *(float2*)(Ob + (size_t)gr1 * Dd + col) = make_float2(acc[nt][2], acc[nt][3]);
    }
}

// ============================================================================
extern "C" void kernel_launch(void* const* d_in, const int* in_sizes, int n_in,
                              void* d_out, int out_size) {
    const float* Q = (const float*)d_in[0];
    const float* K = (const float*)d_in[1];
    const float* V = (const float*)d_in[2];
    const int*   M = (const int*)d_in[3];

    float* out  = (float*)d_out;
    float* attn = out + (size_t)Bb * Hh * Ss * Dd;

    constexpr K2 DK = threefry_host(0u, 42u, 0u, 7u);

    cudaFuncSetAttribute(qk_kernel, cudaFuncAttributeMaxDynamicSharedMemorySize,
                         QK_SMEM_BYTES);
    cudaFuncSetAttribute(pv_kernel, cudaFuncAttributeMaxDynamicSharedMemorySize,
                         PV_SMEM_BYTES);

    qk_kernel<<<dim3(16, 8, 128), 256, QK_SMEM_BYTES>>>(Q, K, M, attn);
    pv_kernel<<<dim3(8, 128), 256, PV_SMEM_BYTES>>>(attn, V, out, DK.a, DK.b);
}